// round 3
// baseline (speedup 1.0000x reference)
#include <cuda_runtime.h>
#include <cuda_fp16.h>
#include <cstdint>

// Problem shape
#define KM 4096   // rows of x / out
#define KP 4096   // inner dim
#define KN 8192   // rows of weight / cols of out

// GEMM tiling
#define BM 128
#define BN 256
#define BK 64
#define STAGES 3
#define KSTEPS (KP / BK)                 // 64
#define A_STAGE_BYTES (BM * BK * 2)      // 16384
#define B_STAGE_BYTES (BN * BK * 2)      // 32768
#define STAGE_BYTES (A_STAGE_BYTES + B_STAGE_BYTES)   // 49152
#define SMEM_TOTAL (STAGES * STAGE_BYTES)             // 147456

// fp16 scratch (row-major)
__device__ __half g_Xh[(size_t)KM * KP];   // 32 MB
__device__ __half g_Wh[(size_t)KN * KP];   // 64 MB

// ---------------------------------------------------------------------------
__device__ __forceinline__ uint32_t s2u(const void* p) {
    uint32_t a;
    asm("{ .reg .u64 t; cvta.to.shared.u64 t, %1; cvt.u32.u64 %0, t; }"
        : "=r"(a) : "l"(p));
    return a;
}

__device__ __forceinline__ void cp_async16(uint32_t dst, const void* src) {
    asm volatile("cp.async.cg.shared.global [%0], [%1], 16;" :: "r"(dst), "l"(src));
}
__device__ __forceinline__ void cp_commit() {
    asm volatile("cp.async.commit_group;" ::: "memory");
}
template <int N>
__device__ __forceinline__ void cp_wait() {
    asm volatile("cp.async.wait_group %0;" :: "n"(N) : "memory");
}

__device__ __forceinline__ void ldsm_x4(uint32_t* r, uint32_t addr) {
    asm volatile("ldmatrix.sync.aligned.m8n8.x4.shared.b16 {%0,%1,%2,%3}, [%4];"
                 : "=r"(r[0]), "=r"(r[1]), "=r"(r[2]), "=r"(r[3]) : "r"(addr));
}

#define MMA16816(d, a, b0, b1)                                          \
    asm volatile(                                                       \
        "mma.sync.aligned.m16n8k16.row.col.f32.f16.f16.f32 "            \
        "{%0,%1,%2,%3}, {%4,%5,%6,%7}, {%8,%9}, {%0,%1,%2,%3};"         \
        : "+f"((d)[0]), "+f"((d)[1]), "+f"((d)[2]), "+f"((d)[3])        \
        : "r"((a)[0]), "r"((a)[1]), "r"((a)[2]), "r"((a)[3]),           \
          "r"(b0), "r"(b1))

// swizzled byte offset within a [rows x 64-half] tile (128B rows, 16B chunks)
__device__ __forceinline__ uint32_t swz(int row, int chunk) {
    return (uint32_t)row * 128u + (uint32_t)((chunk ^ (row & 7)) << 4);
}

// ---------------------------------------------------------------------------
// Pass 1: fp32 -> fp16 row-major copy (8 elems / thread)
// ---------------------------------------------------------------------------
__global__ void __launch_bounds__(256) convert_kernel(const float* __restrict__ src,
                                                      __half* __restrict__ dst, int n8) {
    int i = blockIdx.x * 256 + threadIdx.x;
    if (i >= n8) return;
    const float4* s = reinterpret_cast<const float4*>(src) + (size_t)i * 2;
    float4 f0 = s[0];
    float4 f1 = s[1];
    alignas(16) __half2 h[4];
    h[0] = __floats2half2_rn(f0.x, f0.y);
    h[1] = __floats2half2_rn(f0.z, f0.w);
    h[2] = __floats2half2_rn(f1.x, f1.y);
    h[3] = __floats2half2_rn(f1.z, f1.w);
    reinterpret_cast<uint4*>(dst)[i] = *reinterpret_cast<const uint4*>(h);
}

// ---------------------------------------------------------------------------
// Pass 2: mma.sync fp16 GEMM, 128x256 CTA tile, 3-stage cp.async pipeline.
// 8 warps: warp tile 64x64. warp_m = wid&1, warp_n = wid>>1.
// ---------------------------------------------------------------------------
__global__ void __launch_bounds__(256, 1) gemm_kernel(const float* __restrict__ bias,
                                                      float* __restrict__ out) {
    extern __shared__ char smem[];
    const uint32_t sb = s2u(smem);
    const int tid = threadIdx.x;
    const int lane = tid & 31;
    const int wid = tid >> 5;
    const int nt = blockIdx.x;   // 0..31
    const int mt = blockIdx.y;   // 0..31

    const __half* gA0 = g_Xh + (size_t)(mt * BM) * KP;
    const __half* gW0 = g_Wh + (size_t)(nt * BN) * KP;

    // per-thread load slots: 4 A chunks + 8 B chunks of 16B each
    auto load_stage = [&](int ks, int buf) {
        uint32_t sA = sb + buf * STAGE_BYTES;
        uint32_t sB = sA + A_STAGE_BYTES;
        const __half* gA = gA0 + ks * BK;
        const __half* gB = gW0 + ks * BK;
        #pragma unroll
        for (int i = 0; i < 4; i++) {
            int idx = i * 256 + tid;
            int r = idx >> 3, c = idx & 7;
            cp_async16(sA + swz(r, c), gA + (size_t)r * KP + c * 8);
        }
        #pragma unroll
        for (int i = 0; i < 8; i++) {
            int idx = i * 256 + tid;
            int r = idx >> 3, c = idx & 7;
            cp_async16(sB + swz(r, c), gB + (size_t)r * KP + c * 8);
        }
    };

    // prologue: stages 0 .. STAGES-2
    #pragma unroll
    for (int s = 0; s < STAGES - 1; s++) {
        load_stage(s, s);
        cp_commit();
    }

    const int wm = (wid & 1) * 64;
    const int wn = (wid >> 1) * 64;

    float acc[4][8][4];
    #pragma unroll
    for (int mi = 0; mi < 4; mi++)
        #pragma unroll
        for (int ni = 0; ni < 8; ni++)
            #pragma unroll
            for (int q = 0; q < 4; q++) acc[mi][ni][q] = 0.0f;

    // ldmatrix lane addressing (constant over the loop)
    const int arow = lane & 15;           // A: row within m16 tile
    const int achunk = lane >> 4;         // A: 16B chunk parity (k0-7 vs k8-15)
    const int brow = (lane & 7) + ((lane >> 4) << 3);  // B: row within n16 pair
    const int bchunk = (lane >> 3) & 1;   // B: 16B chunk parity

    for (int ks = 0; ks < KSTEPS; ks++) {
        cp_wait<STAGES - 2>();
        __syncthreads();

        if (ks + STAGES - 1 < KSTEPS)
            load_stage(ks + STAGES - 1, (ks + STAGES - 1) % STAGES);
        cp_commit();

        uint32_t sA = sb + (ks % STAGES) * STAGE_BYTES;
        uint32_t sB = sA + A_STAGE_BYTES;

        #pragma unroll
        for (int kk = 0; kk < BK / 16; kk++) {
            uint32_t a[4][4], b[4][4];
            #pragma unroll
            for (int mi = 0; mi < 4; mi++) {
                int row = wm + mi * 16 + arow;
                ldsm_x4(a[mi], sA + swz(row, kk * 2 + achunk));
            }
            #pragma unroll
            for (int nj = 0; nj < 4; nj++) {
                int row = wn + nj * 16 + brow;
                ldsm_x4(b[nj], sB + swz(row, kk * 2 + bchunk));
            }
            #pragma unroll
            for (int mi = 0; mi < 4; mi++)
                #pragma unroll
                for (int ni = 0; ni < 8; ni++)
                    MMA16816(acc[mi][ni], a[mi],
                             b[ni >> 1][(ni & 1) * 2], b[ni >> 1][(ni & 1) * 2 + 1]);
        }
    }

    // ---- epilogue: direct gmem stores with bias ----
    const int orow0 = mt * BM + wm + (lane >> 2);
    const int ocol0 = nt * BN + wn + (lane & 3) * 2;

    #pragma unroll
    for (int ni = 0; ni < 8; ni++) {
        int col = ocol0 + ni * 8;
        float2 bv = *reinterpret_cast<const float2*>(bias + col);
        #pragma unroll
        for (int mi = 0; mi < 4; mi++) {
            int r0 = orow0 + mi * 16;
            float2 o0, o1;
            o0.x = acc[mi][ni][0] + bv.x;
            o0.y = acc[mi][ni][1] + bv.y;
            o1.x = acc[mi][ni][2] + bv.x;
            o1.y = acc[mi][ni][3] + bv.y;
            *reinterpret_cast<float2*>(out + (size_t)r0 * KN + col) = o0;
            *reinterpret_cast<float2*>(out + (size_t)(r0 + 8) * KN + col) = o1;
        }
    }
}

// ---------------------------------------------------------------------------
extern "C" void kernel_launch(void* const* d_in, const int* in_sizes, int n_in,
                              void* d_out, int out_size) {
    const float* x    = (const float*)d_in[0];   // [4096, 4096]
    const float* w    = (const float*)d_in[1];   // [8192, 4096]
    const float* bias = (const float*)d_in[2];   // [8192]
    float* out = (float*)d_out;                  // [4096, 8192]

    __half* xh;  cudaGetSymbolAddress((void**)&xh, g_Xh);
    __half* wh;  cudaGetSymbolAddress((void**)&wh, g_Wh);

    cudaFuncSetAttribute(gemm_kernel, cudaFuncAttributeMaxDynamicSharedMemorySize, SMEM_TOTAL);

    convert_kernel<<<(KM * KP / 8) / 256, 256>>>(x, xh, KM * KP / 8);
    convert_kernel<<<(KN * KP / 8) / 256, 256>>>(w, wh, KN * KP / 8);

    dim3 grid(KN / BN, KM / BM);   // (32, 32)
    gemm_kernel<<<grid, 256, SMEM_TOTAL>>>(bias, out);
}

// round 4
// speedup vs baseline: 1.0773x; 1.0773x over previous
#include <cuda_runtime.h>
#include <cuda_fp16.h>
#include <cstdint>

// Problem shape
#define KM 4096   // rows of x / out
#define KP 4096   // inner dim
#define KN 8192   // rows of weight / cols of out

// GEMM tiling
#define BM 128
#define BN 128
#define BK 64
#define STAGES 3
#define KSTEPS (KP / BK)                 // 64
#define A_STAGE_BYTES (BM * BK * 2)      // 16384
#define B_STAGE_BYTES (BN * BK * 2)      // 16384
#define STAGE_BYTES (A_STAGE_BYTES + B_STAGE_BYTES)   // 32768
#define SMEM_TOTAL (STAGES * STAGE_BYTES)             // 98304

// fp16 scratch (row-major)
__device__ __half g_Xh[(size_t)KM * KP];   // 32 MB
__device__ __half g_Wh[(size_t)KN * KP];   // 64 MB

#define NX8 ((KM * KP) / 8)   // 2097152 x-chunks
#define NW8 ((KN * KP) / 8)   // 4194304 w-chunks

// ---------------------------------------------------------------------------
__device__ __forceinline__ uint32_t s2u(const void* p) {
    uint32_t a;
    asm("{ .reg .u64 t; cvta.to.shared.u64 t, %1; cvt.u32.u64 %0, t; }"
        : "=r"(a) : "l"(p));
    return a;
}

__device__ __forceinline__ void cp_async16(uint32_t dst, const void* src) {
    asm volatile("cp.async.cg.shared.global [%0], [%1], 16;" :: "r"(dst), "l"(src));
}
__device__ __forceinline__ void cp_commit() {
    asm volatile("cp.async.commit_group;" ::: "memory");
}
template <int N>
__device__ __forceinline__ void cp_wait() {
    asm volatile("cp.async.wait_group %0;" :: "n"(N) : "memory");
}

__device__ __forceinline__ void ldsm_x4(uint32_t* r, uint32_t addr) {
    asm volatile("ldmatrix.sync.aligned.m8n8.x4.shared.b16 {%0,%1,%2,%3}, [%4];"
                 : "=r"(r[0]), "=r"(r[1]), "=r"(r[2]), "=r"(r[3]) : "r"(addr));
}

#define MMA16816(d, a, b0, b1)                                          \
    asm volatile(                                                       \
        "mma.sync.aligned.m16n8k16.row.col.f32.f16.f16.f32 "            \
        "{%0,%1,%2,%3}, {%4,%5,%6,%7}, {%8,%9}, {%0,%1,%2,%3};"         \
        : "+f"((d)[0]), "+f"((d)[1]), "+f"((d)[2]), "+f"((d)[3])        \
        : "r"((a)[0]), "r"((a)[1]), "r"((a)[2]), "r"((a)[3]),           \
          "r"(b0), "r"(b1))

// swizzled byte offset within a [rows x 64-half] tile (128B rows, 16B chunks)
__device__ __forceinline__ uint32_t swz(int row, int chunk) {
    return (uint32_t)row * 128u + (uint32_t)((chunk ^ (row & 7)) << 4);
}

// ---------------------------------------------------------------------------
// Pass 1: fp32 -> fp16 for BOTH x and weight in a single launch
// (single kernel keeps the launch pattern 2-periodic so ncu -s 5 -c 1
//  lands on the GEMM, and slightly improves tail utilization)
// ---------------------------------------------------------------------------
__global__ void __launch_bounds__(256) convert_all_kernel(const float* __restrict__ x,
                                                          const float* __restrict__ w) {
    int i = blockIdx.x * 256 + threadIdx.x;
    const float* src;
    __half* dst;
    int j;
    if (i < NX8) {
        src = x;  dst = g_Xh;  j = i;
    } else {
        src = w;  dst = g_Wh;  j = i - NX8;
        if (j >= NW8) return;
    }
    const float4* s = reinterpret_cast<const float4*>(src) + (size_t)j * 2;
    float4 f0 = s[0];
    float4 f1 = s[1];
    alignas(16) __half2 h[4];
    h[0] = __floats2half2_rn(f0.x, f0.y);
    h[1] = __floats2half2_rn(f0.z, f0.w);
    h[2] = __floats2half2_rn(f1.x, f1.y);
    h[3] = __floats2half2_rn(f1.z, f1.w);
    reinterpret_cast<uint4*>(dst)[j] = *reinterpret_cast<const uint4*>(h);
}

// ---------------------------------------------------------------------------
// Pass 2: mma.sync fp16 GEMM, 128x128 tile, 3-stage cp.async pipeline.
// 8 warps, warp tile 64x32. __launch_bounds__(256,2) forces 2 CTAs/SM
// (16 warps/SM) for latency hiding; smem 96KB/CTA fits 2 CTAs in 227KB.
// ---------------------------------------------------------------------------
__global__ void __launch_bounds__(256, 2) gemm_kernel(const float* __restrict__ bias,
                                                      float* __restrict__ out) {
    extern __shared__ char smem[];
    const uint32_t sb = s2u(smem);
    const int tid = threadIdx.x;
    const int lane = tid & 31;
    const int wid = tid >> 5;
    const int nt = blockIdx.x;   // 0..63
    const int mt = blockIdx.y;   // 0..31

    const __half* gA0 = g_Xh + (size_t)(mt * BM) * KP;
    const __half* gW0 = g_Wh + (size_t)(nt * BN) * KP;

    // per-thread load slots: 4 A chunks + 4 B chunks of 16B each
    int lrow[4], lcol[4];
    #pragma unroll
    for (int i = 0; i < 4; i++) {
        int idx = i * 256 + tid;
        lrow[i] = idx >> 3;
        lcol[i] = idx & 7;
    }

    auto load_stage = [&](int ks, int buf) {
        uint32_t sA = sb + buf * STAGE_BYTES;
        uint32_t sB = sA + A_STAGE_BYTES;
        const __half* gA = gA0 + ks * BK;
        const __half* gB = gW0 + ks * BK;
        #pragma unroll
        for (int i = 0; i < 4; i++) {
            uint32_t off = swz(lrow[i], lcol[i]);
            cp_async16(sA + off, gA + (size_t)lrow[i] * KP + lcol[i] * 8);
            cp_async16(sB + off, gB + (size_t)lrow[i] * KP + lcol[i] * 8);
        }
    };

    // prologue: stages 0 .. STAGES-2
    #pragma unroll
    for (int s = 0; s < STAGES - 1; s++) {
        load_stage(s, s);
        cp_commit();
    }

    const int wm = (wid & 1) * 64;
    const int wn = (wid >> 1) * 32;

    float acc[4][4][4];
    #pragma unroll
    for (int mi = 0; mi < 4; mi++)
        #pragma unroll
        for (int ni = 0; ni < 4; ni++)
            #pragma unroll
            for (int q = 0; q < 4; q++) acc[mi][ni][q] = 0.0f;

    // ldmatrix lane addressing (constant over the loop)
    const int arow = lane & 15;           // A: row within m16 tile
    const int achunk = lane >> 4;         // A: 16B chunk parity (k0-7 vs k8-15)
    const int brow = (lane & 7) + ((lane >> 4) << 3);  // B: row within n16 pair
    const int bchunk = (lane >> 3) & 1;   // B: 16B chunk parity

    for (int ks = 0; ks < KSTEPS; ks++) {
        cp_wait<STAGES - 2>();
        __syncthreads();

        if (ks + STAGES - 1 < KSTEPS)
            load_stage(ks + STAGES - 1, (ks + STAGES - 1) % STAGES);
        cp_commit();

        uint32_t sA = sb + (ks % STAGES) * STAGE_BYTES;
        uint32_t sB = sA + A_STAGE_BYTES;

        #pragma unroll
        for (int kk = 0; kk < BK / 16; kk++) {
            uint32_t a[4][4], b[2][4];
            #pragma unroll
            for (int mi = 0; mi < 4; mi++) {
                int row = wm + mi * 16 + arow;
                ldsm_x4(a[mi], sA + swz(row, kk * 2 + achunk));
            }
            #pragma unroll
            for (int nj = 0; nj < 2; nj++) {
                int row = wn + nj * 16 + brow;
                ldsm_x4(b[nj], sB + swz(row, kk * 2 + bchunk));
            }
            #pragma unroll
            for (int mi = 0; mi < 4; mi++)
                #pragma unroll
                for (int ni = 0; ni < 4; ni++)
                    MMA16816(acc[mi][ni], a[mi],
                             b[ni >> 1][(ni & 1) * 2], b[ni >> 1][(ni & 1) * 2 + 1]);
        }
    }

    // ---- epilogue: direct gmem stores with bias ----
    const int orow0 = mt * BM + wm + (lane >> 2);
    const int ocol0 = nt * BN + wn + (lane & 3) * 2;

    #pragma unroll
    for (int ni = 0; ni < 4; ni++) {
        int col = ocol0 + ni * 8;
        float2 bv = *reinterpret_cast<const float2*>(bias + col);
        #pragma unroll
        for (int mi = 0; mi < 4; mi++) {
            int r0 = orow0 + mi * 16;
            float2 o0, o1;
            o0.x = acc[mi][ni][0] + bv.x;
            o0.y = acc[mi][ni][1] + bv.y;
            o1.x = acc[mi][ni][2] + bv.x;
            o1.y = acc[mi][ni][3] + bv.y;
            *reinterpret_cast<float2*>(out + (size_t)r0 * KN + col) = o0;
            *reinterpret_cast<float2*>(out + (size_t)(r0 + 8) * KN + col) = o1;
        }
    }
}

// ---------------------------------------------------------------------------
extern "C" void kernel_launch(void* const* d_in, const int* in_sizes, int n_in,
                              void* d_out, int out_size) {
    const float* x    = (const float*)d_in[0];   // [4096, 4096]
    const float* w    = (const float*)d_in[1];   // [8192, 4096]
    const float* bias = (const float*)d_in[2];   // [8192]
    float* out = (float*)d_out;                  // [4096, 8192]

    cudaFuncSetAttribute(gemm_kernel, cudaFuncAttributeMaxDynamicSharedMemorySize, SMEM_TOTAL);

    convert_all_kernel<<<(NX8 + NW8) / 256, 256>>>(x, w);

    dim3 grid(KN / BN, KM / BM);   // (64, 32)
    gemm_kernel<<<grid, 256, SMEM_TOTAL>>>(bias, out);
}

// round 5
// speedup vs baseline: 1.1166x; 1.0365x over previous
#include <cuda_runtime.h>
#include <cuda_fp16.h>
#include <cstdint>

// Problem shape
#define KM 4096   // rows of x / out
#define KP 4096   // inner dim
#define KN 8192   // rows of weight / cols of out

// GEMM tiling: CTA 128x128, 4 warps, warp tile 64x64
#define BM 128
#define BN 128
#define BK 64
#define STAGES 3
#define KSTEPS (KP / BK)                 // 64
#define A_STAGE_BYTES (BM * BK * 2)      // 16384
#define B_STAGE_BYTES (BN * BK * 2)      // 16384
#define STAGE_BYTES (A_STAGE_BYTES + B_STAGE_BYTES)   // 32768
#define SMEM_TOTAL (STAGES * STAGE_BYTES)             // 98304

// fp16 scratch (row-major)
__device__ __half g_Xh[(size_t)KM * KP];   // 32 MB
__device__ __half g_Wh[(size_t)KN * KP];   // 64 MB

#define NX8 ((KM * KP) / 8)   // 2097152 x-chunks
#define NW8 ((KN * KP) / 8)   // 4194304 w-chunks

// ---------------------------------------------------------------------------
__device__ __forceinline__ uint32_t s2u(const void* p) {
    uint32_t a;
    asm("{ .reg .u64 t; cvta.to.shared.u64 t, %1; cvt.u32.u64 %0, t; }"
        : "=r"(a) : "l"(p));
    return a;
}

__device__ __forceinline__ void cp_async16(uint32_t dst, const void* src) {
    asm volatile("cp.async.cg.shared.global [%0], [%1], 16;" :: "r"(dst), "l"(src));
}
__device__ __forceinline__ void cp_commit() {
    asm volatile("cp.async.commit_group;" ::: "memory");
}
template <int N>
__device__ __forceinline__ void cp_wait() {
    asm volatile("cp.async.wait_group %0;" :: "n"(N) : "memory");
}

__device__ __forceinline__ void ldsm_x4(uint32_t* r, uint32_t addr) {
    asm volatile("ldmatrix.sync.aligned.m8n8.x4.shared.b16 {%0,%1,%2,%3}, [%4];"
                 : "=r"(r[0]), "=r"(r[1]), "=r"(r[2]), "=r"(r[3]) : "r"(addr));
}

#define MMA16816(d, a, b0, b1)                                          \
    asm volatile(                                                       \
        "mma.sync.aligned.m16n8k16.row.col.f32.f16.f16.f32 "            \
        "{%0,%1,%2,%3}, {%4,%5,%6,%7}, {%8,%9}, {%0,%1,%2,%3};"         \
        : "+f"((d)[0]), "+f"((d)[1]), "+f"((d)[2]), "+f"((d)[3])        \
        : "r"((a)[0]), "r"((a)[1]), "r"((a)[2]), "r"((a)[3]),           \
          "r"(b0), "r"(b1))

// swizzled byte offset within a [rows x 64-half] tile (128B rows, 16B chunks)
__device__ __forceinline__ uint32_t swz(int row, int chunk) {
    return (uint32_t)row * 128u + (uint32_t)((chunk ^ (row & 7)) << 4);
}

// ---------------------------------------------------------------------------
// Pass 1: fp32 -> fp16 for BOTH x and weight in a single launch
// ---------------------------------------------------------------------------
__global__ void __launch_bounds__(256) convert_all_kernel(const float* __restrict__ x,
                                                          const float* __restrict__ w) {
    int i = blockIdx.x * 256 + threadIdx.x;
    const float* src;
    __half* dst;
    int j;
    if (i < NX8) {
        src = x;  dst = g_Xh;  j = i;
    } else {
        src = w;  dst = g_Wh;  j = i - NX8;
        if (j >= NW8) return;
    }
    const float4* s = reinterpret_cast<const float4*>(src) + (size_t)j * 2;
    float4 f0 = s[0];
    float4 f1 = s[1];
    alignas(16) __half2 h[4];
    h[0] = __floats2half2_rn(f0.x, f0.y);
    h[1] = __floats2half2_rn(f0.z, f0.w);
    h[2] = __floats2half2_rn(f1.x, f1.y);
    h[3] = __floats2half2_rn(f1.z, f1.w);
    reinterpret_cast<uint4*>(dst)[j] = *reinterpret_cast<const uint4*>(h);
}

// ---------------------------------------------------------------------------
// Pass 2: mma.sync fp16 GEMM, 128x128 CTA tile, 4 warps (warp tile 64x64),
// 3-stage cp.async pipeline. 2 CTAs/SM (RF ~48K/64K, smem 192KB/227KB).
// Warp-tile 64x64 cuts LDSM bytes/MMA from 192 to 128 (smem crossbar was
// at 80% of the 128 B/cyc cap and binding the tensor pipe at 73%).
// ---------------------------------------------------------------------------
__global__ void __launch_bounds__(128, 2) gemm_kernel(const float* __restrict__ bias,
                                                      float* __restrict__ out) {
    extern __shared__ char smem[];
    const uint32_t sb = s2u(smem);
    const int tid = threadIdx.x;
    const int lane = tid & 31;
    const int wid = tid >> 5;   // 0..3
    const int nt = blockIdx.x;  // 0..63
    const int mt = blockIdx.y;  // 0..31

    const __half* gA0 = g_Xh + (size_t)(mt * BM) * KP;
    const __half* gW0 = g_Wh + (size_t)(nt * BN) * KP;

    // per-thread load slots: 8 A chunks + 8 B chunks of 16B each (128 threads)
    int lrow[8], lcol[8];
    #pragma unroll
    for (int i = 0; i < 8; i++) {
        int idx = i * 128 + tid;
        lrow[i] = idx >> 3;
        lcol[i] = idx & 7;
    }

    auto load_stage = [&](int ks, int buf) {
        uint32_t sA = sb + buf * STAGE_BYTES;
        uint32_t sB = sA + A_STAGE_BYTES;
        const __half* gA = gA0 + ks * BK;
        const __half* gB = gW0 + ks * BK;
        #pragma unroll
        for (int i = 0; i < 8; i++) {
            uint32_t off = swz(lrow[i], lcol[i]);
            cp_async16(sA + off, gA + (size_t)lrow[i] * KP + lcol[i] * 8);
            cp_async16(sB + off, gB + (size_t)lrow[i] * KP + lcol[i] * 8);
        }
    };

    // prologue: stages 0 .. STAGES-2
    #pragma unroll
    for (int s = 0; s < STAGES - 1; s++) {
        load_stage(s, s);
        cp_commit();
    }

    const int wm = (wid & 1) * 64;
    const int wn = (wid >> 1) * 64;

    float acc[4][8][4];
    #pragma unroll
    for (int mi = 0; mi < 4; mi++)
        #pragma unroll
        for (int ni = 0; ni < 8; ni++)
            #pragma unroll
            for (int q = 0; q < 4; q++) acc[mi][ni][q] = 0.0f;

    // ldmatrix lane addressing (constant over the loop)
    const int arow = lane & 15;           // A: row within m16 tile
    const int achunk = lane >> 4;         // A: 16B chunk parity (k0-7 vs k8-15)
    const int brow = (lane & 7) + ((lane >> 4) << 3);  // B: row within n16 pair
    const int bchunk = (lane >> 3) & 1;   // B: 16B chunk parity

    for (int ks = 0; ks < KSTEPS; ks++) {
        cp_wait<STAGES - 2>();
        __syncthreads();

        if (ks + STAGES - 1 < KSTEPS)
            load_stage(ks + STAGES - 1, (ks + STAGES - 1) % STAGES);
        cp_commit();

        uint32_t sA = sb + (ks % STAGES) * STAGE_BYTES;
        uint32_t sB = sA + A_STAGE_BYTES;

        #pragma unroll
        for (int kk = 0; kk < BK / 16; kk++) {
            uint32_t a[4][4], b[4][4];
            #pragma unroll
            for (int mi = 0; mi < 4; mi++) {
                int row = wm + mi * 16 + arow;
                ldsm_x4(a[mi], sA + swz(row, kk * 2 + achunk));
            }
            #pragma unroll
            for (int nj = 0; nj < 4; nj++) {
                int row = wn + nj * 16 + brow;
                ldsm_x4(b[nj], sB + swz(row, kk * 2 + bchunk));
            }
            #pragma unroll
            for (int mi = 0; mi < 4; mi++)
                #pragma unroll
                for (int ni = 0; ni < 8; ni++)
                    MMA16816(acc[mi][ni], a[mi],
                             b[ni >> 1][(ni & 1) * 2], b[ni >> 1][(ni & 1) * 2 + 1]);
        }
    }

    // ---- epilogue: direct gmem stores with bias ----
    const int orow0 = mt * BM + wm + (lane >> 2);
    const int ocol0 = nt * BN + wn + (lane & 3) * 2;

    #pragma unroll
    for (int ni = 0; ni < 8; ni++) {
        int col = ocol0 + ni * 8;
        float2 bv = *reinterpret_cast<const float2*>(bias + col);
        #pragma unroll
        for (int mi = 0; mi < 4; mi++) {
            int r0 = orow0 + mi * 16;
            float2 o0, o1;
            o0.x = acc[mi][ni][0] + bv.x;
            o0.y = acc[mi][ni][1] + bv.y;
            o1.x = acc[mi][ni][2] + bv.x;
            o1.y = acc[mi][ni][3] + bv.y;
            *reinterpret_cast<float2*>(out + (size_t)r0 * KN + col) = o0;
            *reinterpret_cast<float2*>(out + (size_t)(r0 + 8) * KN + col) = o1;
        }
    }
}

// ---------------------------------------------------------------------------
extern "C" void kernel_launch(void* const* d_in, const int* in_sizes, int n_in,
                              void* d_out, int out_size) {
    const float* x    = (const float*)d_in[0];   // [4096, 4096]
    const float* w    = (const float*)d_in[1];   // [8192, 4096]
    const float* bias = (const float*)d_in[2];   // [8192]
    float* out = (float*)d_out;                  // [4096, 8192]

    cudaFuncSetAttribute(gemm_kernel, cudaFuncAttributeMaxDynamicSharedMemorySize, SMEM_TOTAL);

    convert_all_kernel<<<(NX8 + NW8) / 256, 256>>>(x, w);

    dim3 grid(KN / BN, KM / BM);   // (64, 32)
    gemm_kernel<<<grid, 128, SMEM_TOTAL>>>(bias, out);
}